// round 11
// baseline (speedup 1.0000x reference)
#include <cuda_runtime.h>

#define NN 8192
#define NE 16384
#define GRID 148
#define TPB 1024
#define NG 2048          // 8-column groups
#define JMAX 64          // row iterations per thread (8192 / 128)

// ---- scratch (device globals; no allocation allowed) ----
__device__ float g_u[NN];
__device__ float g_v[NN];
__device__ float g_c[NN];
__device__ float g_outp[GRID][NN];

__device__ __forceinline__ float ldcg(const float* p) {   // DRAM stream -> L2 resident
    float r;
    asm volatile("ld.global.cg.f32 %0, [%1];" : "=f"(r) : "l"(p));
    return r;
}
__device__ __forceinline__ float ldcs(const float* p) {   // evict-first (last touch)
    float r;
    asm volatile("ld.global.cs.f32 %0, [%1];" : "=f"(r) : "l"(p));
    return r;
}

// K1: per-node scalars u = X·k1, v = X·k2, c = X·k3
__global__ void k1_prep(const float* __restrict__ X, const float* __restrict__ kw) {
    int n = blockIdx.x * blockDim.x + threadIdx.x;
    if (n >= NN) return;
    float4 x = reinterpret_cast<const float4*>(X)[n];
    g_u[n] = x.x * kw[0] + x.y * kw[1] + x.z * kw[2]  + x.w * kw[3];
    g_v[n] = x.x * kw[4] + x.y * kw[5] + x.z * kw[6]  + x.w * kw[7];
    g_c[n] = x.x * kw[8] + x.y * kw[9] + x.z * kw[10] + x.w * kw[11];
}

// Main: column-partitioned, fully CTA-local. Per 8-col group:
//   P1 (DRAM, ld.cg): wi[c] = e_c * sum_n Ro[n,c] u[n];  wo[c] = e_c * sum_n Ri[n,c] v[n]
//   P2 (L2, ld.cs):   sout[n] += Ri[n,c] wi[c] + Ro[n,c] wo[c]
__global__ __launch_bounds__(TPB, 1) void big(const float* __restrict__ Ri,
                                              const float* __restrict__ Ro,
                                              const float* __restrict__ ew) {
    __shared__ float su[NN];       // 32 KB
    __shared__ float sv[NN];       // 32 KB
    __shared__ float sout[NN];     // 32 KB
    __shared__ float swi[TPB];     // 4 KB
    __shared__ float swo[TPB];     // 4 KB
    __shared__ float sw[8][2];

    const int t   = threadIdx.x;
    const int cta = blockIdx.x;
    const int c   = t & 7;         // column within group (adjacent lanes!)
    const int q   = t >> 3;        // row phase 0..127

    for (int i = t; i < NN; i += TPB) { su[i] = g_u[i]; sv[i] = g_v[i]; sout[i] = 0.f; }
    __syncthreads();

    const int g0 = (int)(((long long)cta * NG) / GRID);
    const int g1 = (int)(((long long)(cta + 1) * NG) / GRID);

    for (int g = g0; g < g1; ++g) {
        const float* pRi = Ri + (size_t)q * NE + g * 8 + c;
        const float* pRo = Ro + (size_t)q * NE + g * 8 + c;

        // ---- P1: DRAM stream + column dots ----
        float di = 0.f, dv = 0.f;
#pragma unroll 8
        for (int j = 0; j < JMAX; ++j) {
            const int n = q + 128 * j;
            const size_t off = (size_t)j * 128 * NE;
            const float a = ldcg(pRi + off);
            const float b = ldcg(pRo + off);
            di += b * su[n];      // -> wi (uses Ro, u)
            dv += a * sv[n];      // -> wo (uses Ri, v)
        }
        swi[t] = di; swo[t] = dv;
        __syncthreads();
        // tree reduce over q (stride-8 keeps column identity)
#pragma unroll
        for (int off = TPB / 2; off >= 8; off >>= 1) {
            if (t < off) { swi[t] += swi[t + off]; swo[t] += swo[t + off]; }
            __syncthreads();
        }
        if (t < 8) {
            const float e_ = ew[g * 8 + t];
            sw[t][0] = e_ * swi[t];
            sw[t][1] = e_ * swo[t];
        }
        __syncthreads();
        const float wi = sw[c][0];
        const float wo = sw[c][1];

        // ---- P2: L2 re-read (evict-first) + row accumulation ----
#pragma unroll 8
        for (int j = 0; j < JMAX; ++j) {
            const int n = q + 128 * j;
            const size_t off = (size_t)j * 128 * NE;
            const float a = ldcs(pRi + off);
            const float b = ldcs(pRo + off);
            float contrib = a * wi + b * wo;
            contrib += __shfl_xor_sync(0xffffffffu, contrib, 1);
            contrib += __shfl_xor_sync(0xffffffffu, contrib, 2);
            contrib += __shfl_xor_sync(0xffffffffu, contrib, 4);
            if (c == 0) sout[n] += contrib;
        }
        // no barrier needed: next group's smem writes are fenced by its own tree barriers
    }

    __syncthreads();
    for (int i = t; i < NN; i += TPB) g_outp[cta][i] = sout[i];
}

// Final: out[n] = sum_p outp[p][n] + c[n]   (fixed order, deterministic)
__global__ void kfin(float* __restrict__ out) {
    const int n = blockIdx.x * blockDim.x + threadIdx.x;
    if (n >= NN) return;
    float s = g_c[n];
#pragma unroll 4
    for (int p = 0; p < GRID; ++p) s += g_outp[p][n];
    out[n] = s;
}

extern "C" void kernel_launch(void* const* d_in, const int* in_sizes, int n_in,
                              void* d_out, int out_size) {
    const float* X    = (const float*)d_in[0];  // [N,4]
    const float* ew   = (const float*)d_in[1];  // [E,1]
    const float* Ri   = (const float*)d_in[2];  // [N,E]
    const float* Ro   = (const float*)d_in[3];  // [N,E]
    const float* kern = (const float*)d_in[4];  // [12,1]
    float* out = (float*)d_out;                 // [N,1]

    k1_prep<<<NN / 256, 256>>>(X, kern);
    big<<<GRID, TPB>>>(Ri, Ro, ew);
    kfin<<<NN / 256, 256>>>(out);
}

// round 12
// speedup vs baseline: 3.1505x; 3.1505x over previous
#include <cuda_runtime.h>

#define NN 8192
#define NE 16384
#define NCTA 128         // c = 8b + q : b chain 0..15, q row-eighth 0..7
#define TPB 1024
#define NKR 32           // rounds; group g = b + 16k
#define NGRP 512         // 32-col groups
#define ROWS 1024        // rows per eighth

// ---- scratch (device globals; no allocation allowed) ----
__device__ float g_u[NN];
__device__ float g_v[NN];
__device__ float g_c[NN];
__device__ float g_part[NGRP][8][2][32];   // [group][eighth][wi|wo][col]
__device__ float g_outp[NCTA][ROWS];
__device__ int   g_flag[NGRP][8];

__device__ __forceinline__ int ld_acq(const int* p) {
    int v;
    asm volatile("ld.acquire.gpu.s32 %0, [%1];" : "=r"(v) : "l"(p) : "memory");
    return v;
}
__device__ __forceinline__ void st_rel(int* p, int v) {
    asm volatile("st.release.gpu.s32 [%0], %1;" :: "l"(p), "r"(v) : "memory");
}
__device__ __forceinline__ void f4add(float4& a, const float4 b) {
    a.x += b.x; a.y += b.y; a.z += b.z; a.w += b.w;
}
__device__ __forceinline__ void f4fma(float4& a, const float4 b, float s) {
    a.x += b.x * s; a.y += b.y * s; a.z += b.z * s; a.w += b.w * s;
}
__device__ __forceinline__ float dot4(const float4 a, const float4 b) {
    return a.x * b.x + a.y * b.y + a.z * b.z + a.w * b.w;
}
__device__ __forceinline__ float4 ldcg4(const float* p) {   // DRAM stream -> L2
    float4 r;
    asm volatile("ld.global.cg.v4.f32 {%0,%1,%2,%3}, [%4];"
                 : "=f"(r.x), "=f"(r.y), "=f"(r.z), "=f"(r.w) : "l"(p));
    return r;
}
__device__ __forceinline__ float4 ldcs4(const float* p) {   // evict-first (last touch)
    float4 r;
    asm volatile("ld.global.cs.v4.f32 {%0,%1,%2,%3}, [%4];"
                 : "=f"(r.x), "=f"(r.y), "=f"(r.z), "=f"(r.w) : "l"(p));
    return r;
}
__device__ __forceinline__ void bfly4(float4& a, int off) {
    a.x += __shfl_xor_sync(0xffffffffu, a.x, off);
    a.y += __shfl_xor_sync(0xffffffffu, a.y, off);
    a.z += __shfl_xor_sync(0xffffffffu, a.z, off);
    a.w += __shfl_xor_sync(0xffffffffu, a.w, off);
}

__global__ void k1_prep(const float* __restrict__ X, const float* __restrict__ kw) {
    int n = blockIdx.x * blockDim.x + threadIdx.x;
    int* fl = &g_flag[0][0];
    for (int i = n; i < NGRP * 8; i += NN) fl[i] = 0;
    if (n >= NN) return;
    float4 x = reinterpret_cast<const float4*>(X)[n];
    g_u[n] = x.x * kw[0] + x.y * kw[1] + x.z * kw[2]  + x.w * kw[3];
    g_v[n] = x.x * kw[4] + x.y * kw[5] + x.z * kw[6]  + x.w * kw[7];
    g_c[n] = x.x * kw[8] + x.y * kw[9] + x.z * kw[10] + x.w * kw[11];
}

// Round k: P1 streams tile (g=b+16k, eighth q) from DRAM computing column partials;
//          P2 re-reads tile (g=b+16(k-2)) from L2 (full wi/wo known) into sout.
__global__ __launch_bounds__(TPB, 1) void big(const float* __restrict__ Ri,
                                              const float* __restrict__ Ro,
                                              const float* __restrict__ ew) {
    __shared__ float  su[ROWS], sv[ROWS], sout[ROWS];
    __shared__ float4 sredA[32][8];   // [warp][colquad]
    __shared__ float4 sredB[32][8];
    __shared__ float4 swi[8], swo[8];

    const int t   = threadIdx.x;
    const int c   = blockIdx.x;
    const int b   = c >> 3;          // chain 0..15
    const int q   = c & 7;           // row eighth
    const int rowbase = q * ROWS;
    const int w    = t >> 5;
    const int lane = t & 31;
    const int cq   = lane & 7;       // col quad 0..7
    const int rs   = lane >> 3;      // row sub 0..3

    su[t & (ROWS - 1)] = g_u[rowbase + (t & (ROWS - 1))];
    sv[t & (ROWS - 1)] = g_v[rowbase + (t & (ROWS - 1))];
    sout[t & (ROWS - 1)] = 0.f;
    __syncthreads();

    for (int k = 0; k < NKR + 2; ++k) {
        const int gNew = b + 16 * k;          // valid if k < NKR
        const int gOld = b + 16 * (k - 2);    // valid if k >= 2
        const bool P1 = (k < NKR);
        const bool P2 = (k >= 2);

        if (P2) {
            // wait for the 8 eighth-partials of gOld (published ~2 rounds ago)
            if (w == 0) {
                for (;;) {
                    bool ok = (lane < 8) ? (ld_acq(&g_flag[gOld][lane]) != 0) : true;
                    if (__all_sync(0xffffffffu, ok)) break;
                    __nanosleep(64);
                }
            }
            __syncthreads();
            if (t < 16) {   // build wi/wo: fixed-order sum of 8 partials, scale by e
                const int mat = t >> 3, c2 = t & 7;
                float4 s = make_float4(0.f, 0.f, 0.f, 0.f);
#pragma unroll
                for (int e8 = 0; e8 < 8; ++e8)
                    f4add(s, *reinterpret_cast<const float4*>(&g_part[gOld][e8][mat][c2 * 4]));
                const float4 we = *reinterpret_cast<const float4*>(ew + gOld * 32 + c2 * 4);
                s.x *= we.x; s.y *= we.y; s.z *= we.z; s.w *= we.w;
                if (mat == 0) swi[c2] = s; else swo[c2] = s;
            }
            __syncthreads();
        }

        float4 di = make_float4(0.f, 0.f, 0.f, 0.f);
        float4 dv = make_float4(0.f, 0.f, 0.f, 0.f);
        float4 wi = make_float4(0.f, 0.f, 0.f, 0.f);
        float4 wo = make_float4(0.f, 0.f, 0.f, 0.f);
        if (P2) { wi = swi[cq]; wo = swo[cq]; }
        const size_t colN = (size_t)gNew * 32 + cq * 4;
        const size_t colO = (size_t)gOld * 32 + cq * 4;

#pragma unroll
        for (int step = 0; step < 8; ++step) {
            const int rloc = w * 32 + step * 4 + rs;
            const size_t roff = (size_t)(rowbase + rloc) * NE;
            if (P1) {   // DRAM leg: full-line coalesced stream of tile k
                const float4 a = ldcg4(Ri + roff + colN);
                const float4 bb = ldcg4(Ro + roff + colN);
                f4fma(di, bb, su[rloc]);   // wi partial += Ro * u
                f4fma(dv, a, sv[rloc]);    // wo partial += Ri * v
            }
            if (P2) {   // L2 leg: evict-first re-read of tile k-2
                const float4 a = ldcs4(Ri + roff + colO);
                const float4 bb = ldcs4(Ro + roff + colO);
                float ctr = dot4(a, wi) + dot4(bb, wo);
                ctr += __shfl_xor_sync(0xffffffffu, ctr, 1);
                ctr += __shfl_xor_sync(0xffffffffu, ctr, 2);
                ctr += __shfl_xor_sync(0xffffffffu, ctr, 4);
                if (cq == 0) sout[rloc] += ctr;
            }
        }

        if (P1) {
            // reduce over row-subs (lanes stride 8), leave col sums in rs==0 lanes
            bfly4(di, 8); bfly4(di, 16);
            bfly4(dv, 8); bfly4(dv, 16);
            if (rs == 0) { sredA[w][cq] = di; sredB[w][cq] = dv; }
            __syncthreads();
            if (t < 16) {   // fixed-order cross-warp sum, publish partial
                const int mat = t >> 3, c2 = t & 7;
                float4 s = make_float4(0.f, 0.f, 0.f, 0.f);
#pragma unroll
                for (int w2 = 0; w2 < 32; ++w2)
                    f4add(s, mat ? sredB[w2][c2] : sredA[w2][c2]);
                *reinterpret_cast<float4*>(&g_part[gNew][q][mat][c2 * 4]) = s;
            }
            if (t < 32) {
                __syncwarp();
                __threadfence();
                if (t == 0) st_rel(&g_flag[gNew][q], 1);
            }
        }
        __syncthreads();
    }

    for (int i = t; i < ROWS; i += TPB) g_outp[c][i] = sout[i];
}

// out[n] = sum_b outp[8b + (n>>10)][n & 1023] + c[n]
__global__ void kfin(float* __restrict__ out) {
    const int n = blockIdx.x * blockDim.x + threadIdx.x;
    if (n >= NN) return;
    const int q = n >> 10, i = n & (ROWS - 1);
    float s = g_c[n];
#pragma unroll
    for (int b = 0; b < 16; ++b) s += g_outp[b * 8 + q][i];
    out[n] = s;
}

extern "C" void kernel_launch(void* const* d_in, const int* in_sizes, int n_in,
                              void* d_out, int out_size) {
    const float* X    = (const float*)d_in[0];  // [N,4]
    const float* ew   = (const float*)d_in[1];  // [E,1]
    const float* Ri   = (const float*)d_in[2];  // [N,E]
    const float* Ro   = (const float*)d_in[3];  // [N,E]
    const float* kern = (const float*)d_in[4];  // [12,1]
    float* out = (float*)d_out;                 // [N,1]

    k1_prep<<<NN / 256, 256>>>(X, kern);
    big<<<NCTA, TPB>>>(Ri, Ro, ew);
    kfin<<<NN / 256, 256>>>(out);
}

// round 13
// speedup vs baseline: 3.2785x; 1.0406x over previous
#include <cuda_runtime.h>

#define NN 8192
#define NE 16384
#define NCHAIN 18
#define NCTA (NCHAIN * 8)   // 144
#define TPB 1024
#define NGRP 512            // 32-col groups
#define ROWS 1024           // rows per eighth

// dynamic smem layout (floats)
#define SM_SU   0
#define SM_SV   1024
#define SM_SOUT 2048
#define SM_SACC 3072        // [1024][9] padded
#define SM_SRA  12288       // 256 float4
#define SM_SRB  13312
#define SM_SWI  14336       // 8 float4
#define SM_SWO  14368
#define SMEM_FLOATS 14400
#define SMEM_BYTES (SMEM_FLOATS * 4)

// ---- scratch (device globals; no allocation allowed) ----
__device__ float g_u[NN];
__device__ float g_v[NN];
__device__ float g_c[NN];
__device__ float g_part[NGRP][8][2][32];   // [group][eighth][wi|wo][col]
__device__ float g_outp[NCTA][ROWS];
__device__ int   g_flag[NGRP][8];

__device__ __forceinline__ int ld_acq(const int* p) {
    int v;
    asm volatile("ld.acquire.gpu.s32 %0, [%1];" : "=r"(v) : "l"(p) : "memory");
    return v;
}
__device__ __forceinline__ void st_rel(int* p, int v) {
    asm volatile("st.release.gpu.s32 [%0], %1;" :: "l"(p), "r"(v) : "memory");
}
__device__ __forceinline__ void f4add(float4& a, const float4 b) {
    a.x += b.x; a.y += b.y; a.z += b.z; a.w += b.w;
}
__device__ __forceinline__ void f4fma(float4& a, const float4 b, float s) {
    a.x += b.x * s; a.y += b.y * s; a.z += b.z * s; a.w += b.w * s;
}
__device__ __forceinline__ float dot4(const float4 a, const float4 b) {
    return a.x * b.x + a.y * b.y + a.z * b.z + a.w * b.w;
}
__device__ __forceinline__ float4 ldcg4(const float* p) {   // DRAM stream -> L2
    float4 r;
    asm volatile("ld.global.cg.v4.f32 {%0,%1,%2,%3}, [%4];"
                 : "=f"(r.x), "=f"(r.y), "=f"(r.z), "=f"(r.w) : "l"(p));
    return r;
}
__device__ __forceinline__ float4 ldcs4(const float* p) {   // evict-first (last touch)
    float4 r;
    asm volatile("ld.global.cs.v4.f32 {%0,%1,%2,%3}, [%4];"
                 : "=f"(r.x), "=f"(r.y), "=f"(r.z), "=f"(r.w) : "l"(p));
    return r;
}
__device__ __forceinline__ void bfly4(float4& a, int off) {
    a.x += __shfl_xor_sync(0xffffffffu, a.x, off);
    a.y += __shfl_xor_sync(0xffffffffu, a.y, off);
    a.z += __shfl_xor_sync(0xffffffffu, a.z, off);
    a.w += __shfl_xor_sync(0xffffffffu, a.w, off);
}

__global__ void k1_prep(const float* __restrict__ X, const float* __restrict__ kw) {
    int n = blockIdx.x * blockDim.x + threadIdx.x;
    int* fl = &g_flag[0][0];
    for (int i = n; i < NGRP * 8; i += NN) fl[i] = 0;
    if (n >= NN) return;
    float4 x = reinterpret_cast<const float4*>(X)[n];
    g_u[n] = x.x * kw[0] + x.y * kw[1] + x.z * kw[2]  + x.w * kw[3];
    g_v[n] = x.x * kw[4] + x.y * kw[5] + x.z * kw[6]  + x.w * kw[7];
    g_c[n] = x.x * kw[8] + x.y * kw[9] + x.z * kw[10] + x.w * kw[11];
}

// Round k (chain b, eighth q): P1 streams tile (g=gs+k, q) from DRAM computing
// column partials; P2 re-reads tile (gs+k-2) from L2 against published wi/wo.
__global__ __launch_bounds__(TPB, 1) void big(const float* __restrict__ Ri,
                                              const float* __restrict__ Ro,
                                              const float* __restrict__ ew) {
    extern __shared__ float sm[];
    float*  su    = sm + SM_SU;
    float*  sv    = sm + SM_SV;
    float*  sout  = sm + SM_SOUT;
    float*  sacc  = sm + SM_SACC;
    float4* sredA = reinterpret_cast<float4*>(sm + SM_SRA);   // [32][8]
    float4* sredB = reinterpret_cast<float4*>(sm + SM_SRB);
    float4* swi   = reinterpret_cast<float4*>(sm + SM_SWI);   // [8]
    float4* swo   = reinterpret_cast<float4*>(sm + SM_SWO);

    const int t    = threadIdx.x;
    const int cta  = blockIdx.x;
    const int b    = cta >> 3;       // chain 0..17
    const int q    = cta & 7;        // row eighth
    const int rowbase = q * ROWS;
    const int w    = t >> 5;
    const int lane = t & 31;
    const int cq   = lane & 7;       // col quad 0..7
    const int rs   = lane >> 3;      // row sub 0..3

    su[t] = g_u[rowbase + t];
    sv[t] = g_v[rowbase + t];
    sout[t] = 0.f;
    __syncthreads();

    const int gs = (b * NGRP) / NCHAIN;
    const int ge = ((b + 1) * NGRP) / NCHAIN;
    const int ng = ge - gs;

    for (int k = 0; k <= ng + 1; ++k) {
        const int gNew = gs + k;
        const int gOld = gs + k - 2;
        const bool P1 = (k < ng);
        const bool P2 = (k >= 2);

        if (P2) {
            if (w == 0) {
                for (;;) {
                    bool ok = (lane < 8) ? (ld_acq(&g_flag[gOld][lane]) != 0) : true;
                    if (__all_sync(0xffffffffu, ok)) break;
                    __nanosleep(64);
                }
            }
            __syncthreads();
            if (t < 16) {   // build wi/wo: fixed-order sum of 8 eighth-partials, scale e
                const int mat = t >> 3, c2 = t & 7;
                float4 s = make_float4(0.f, 0.f, 0.f, 0.f);
#pragma unroll
                for (int e8 = 0; e8 < 8; ++e8)
                    f4add(s, *reinterpret_cast<const float4*>(&g_part[gOld][e8][mat][c2 * 4]));
                const float4 we = *reinterpret_cast<const float4*>(ew + gOld * 32 + c2 * 4);
                s.x *= we.x; s.y *= we.y; s.z *= we.z; s.w *= we.w;
                if (mat == 0) swi[c2] = s; else swo[c2] = s;
            }
            __syncthreads();
        }

        float4 wi = make_float4(0.f, 0.f, 0.f, 0.f);
        float4 wo = make_float4(0.f, 0.f, 0.f, 0.f);
        if (P2) { wi = swi[cq]; wo = swo[cq]; }
        float4 di = make_float4(0.f, 0.f, 0.f, 0.f);
        float4 dv = make_float4(0.f, 0.f, 0.f, 0.f);
        float acc[8];
        const size_t colN = (size_t)gNew * 32 + cq * 4;
        const size_t colO = (size_t)gOld * 32 + cq * 4;

#pragma unroll
        for (int step = 0; step < 8; ++step) {
            const int rloc = w * 32 + step * 4 + rs;
            const size_t roff = (size_t)(rowbase + rloc) * NE;
            if (P1) {   // DRAM leg: full-line coalesced stream of tile k
                const float4 a  = ldcg4(Ri + roff + colN);
                const float4 bb = ldcg4(Ro + roff + colN);
                f4fma(di, bb, su[rloc]);   // wi partial += Ro * u
                f4fma(dv, a,  sv[rloc]);   // wo partial += Ri * v
            }
            if (P2) {   // L2 leg: evict-first re-read of tile k-2, register acc
                const float4 a  = ldcs4(Ri + roff + colO);
                const float4 bb = ldcs4(Ro + roff + colO);
                acc[step] = dot4(a, wi) + dot4(bb, wo);
            }
        }

        if (P1) {   // reduce over row-subs within warp; rs==0 lanes hold col sums
            bfly4(di, 8); bfly4(di, 16);
            bfly4(dv, 8); bfly4(dv, 16);
            if (rs == 0) { sredA[w * 8 + cq] = di; sredB[w * 8 + cq] = dv; }
        }
        if (P2) {   // stash per-step dots for the round-end row transpose
#pragma unroll
            for (int step = 0; step < 8; ++step)
                sacc[(w * 32 + step * 4 + rs) * 9 + cq] = acc[step];
        }
        __syncthreads();

        if (P1 && t < 16) {   // fixed-order cross-warp sum, publish partial
            const int mat = t >> 3, c2 = t & 7;
            float4 s = make_float4(0.f, 0.f, 0.f, 0.f);
#pragma unroll
            for (int w2 = 0; w2 < 32; ++w2)
                f4add(s, mat ? sredB[w2 * 8 + c2] : sredA[w2 * 8 + c2]);
            *reinterpret_cast<float4*>(&g_part[gNew][q][mat][c2 * 4]) = s;
        }
        if (P1 && t < 32) {
            __syncwarp();
            __threadfence();
            if (t == 0) st_rel(&g_flag[gNew][q], 1);
        }
        if (P2) {   // row sum: thread t owns row t
            float s2 = 0.f;
#pragma unroll
            for (int c2 = 0; c2 < 8; ++c2) s2 += sacc[t * 9 + c2];
            sout[t] += s2;
        }
        __syncthreads();
    }

    g_outp[cta][t] = sout[t];
}

// out[n] = sum_b outp[b*8 + (n>>10)][n & 1023] + c[n]
__global__ void kfin(float* __restrict__ out) {
    const int n = blockIdx.x * blockDim.x + threadIdx.x;
    if (n >= NN) return;
    const int q = n >> 10, i = n & (ROWS - 1);
    float s = g_c[n];
#pragma unroll
    for (int b = 0; b < NCHAIN; ++b) s += g_outp[b * 8 + q][i];
    out[n] = s;
}

extern "C" void kernel_launch(void* const* d_in, const int* in_sizes, int n_in,
                              void* d_out, int out_size) {
    const float* X    = (const float*)d_in[0];  // [N,4]
    const float* ew   = (const float*)d_in[1];  // [E,1]
    const float* Ri   = (const float*)d_in[2];  // [N,E]
    const float* Ro   = (const float*)d_in[3];  // [N,E]
    const float* kern = (const float*)d_in[4];  // [12,1]
    float* out = (float*)d_out;                 // [N,1]

    cudaFuncSetAttribute(big, cudaFuncAttributeMaxDynamicSharedMemorySize, SMEM_BYTES);
    k1_prep<<<NN / 256, 256>>>(X, kern);
    big<<<NCTA, TPB, SMEM_BYTES>>>(Ri, Ro, ew);
    kfin<<<NN / 256, 256>>>(out);
}